// round 16
// baseline (speedup 1.0000x reference)
#include <cuda_runtime.h>

#define BATCH   64
#define TSTEPS  1024
#define DIM     512
#define NCTA    128          // 8 b-groups x 16 j-groups; co-resident
#define NBG     8
#define NJG     16

#define HSTRIDE 576          // staged row stride: 16 chunks x (32 data + 4 pad)
#define TILEF   (8 * HSTRIDE)
#define PROW    33
#define PSEG    (8 * PROW)

// ---------------- scratch (device globals; no allocations) ------------------
// h stored as (value, tag) pairs: tag == t  <=>  this word holds h_t.
// Ping-pong: h_t lives in buffer t&1. Zero-init = (0.0f, tag 0) = valid h_0.
__device__ uint2 g_h2[2][BATCH * DIM];       // 512 KB

// ---------------- f32x2 packed-FMA helpers (sm_100+) ------------------------
static __device__ __forceinline__ unsigned long long packf2(float lo, float hi) {
    unsigned long long r;
    asm("mov.b64 %0, {%1, %2};" : "=l"(r) : "f"(lo), "f"(hi));
    return r;
}
static __device__ __forceinline__ void unpackf2(unsigned long long v, float& lo, float& hi) {
    asm("mov.b64 {%0, %1}, %2;" : "=f"(lo), "=f"(hi) : "l"(v));
}
static __device__ __forceinline__ unsigned long long fma2(
    unsigned long long a, unsigned long long b, unsigned long long c) {
    unsigned long long d;
    asm("fma.rn.f32x2 %0, %1, %2, %3;" : "=l"(d) : "l"(a), "l"(b), "l"(c));
    return d;
}

// L2-coherent raw accessors for the tagged h buffer (the consumer's gate (tag)
// travels in the same 16B load as the values -> no fences, no atomics).
static __device__ __forceinline__ uint4 ldcg_v4(const void* p) {
    uint4 r;
    asm volatile("ld.global.cg.v4.b32 {%0,%1,%2,%3}, [%4];"
                 : "=r"(r.x), "=r"(r.y), "=r"(r.z), "=r"(r.w) : "l"(p));
    return r;
}
static __device__ __forceinline__ void stcg_v2(void* p, unsigned a, unsigned b) {
    asm volatile("st.global.cg.v2.b32 [%0], {%1,%2};"
                 :: "l"(p), "r"(a), "r"(b) : "memory");
}

// Padded staged-tile address: chunk ch at 36*ch floats (conflict-free LDS.128).
static __device__ __forceinline__ int sw_off(int row, int c4) {
    return row * HSTRIDE + c4 * 4 + (c4 >> 3) * 4;
}

// ---------------------------------------------------------------------------
// Matmul partials: warp w = k-slice 64, lane -> (cg: col pair, ks: k half).
// 8 rows x 2 cols over 32 k. 64 LDS.128 (conflict-free) + 256 fma2 per warp.
// Reads ONLY chunks 2w, 2w+1 of the staged tile.
// ---------------------------------------------------------------------------
static __device__ __forceinline__ void mm_partials(
    const float* __restrict__ sm, const unsigned long long w2[2][16],
    int smoff, int seg, int cg, float* __restrict__ part)
{
    unsigned long long acc[8][2];
#pragma unroll
    for (int r = 0; r < 8; r++) { acc[r][0] = 0ULL; acc[r][1] = 0ULL; }

#pragma unroll
    for (int m = 0; m < 8; m++) {
#pragma unroll
        for (int r = 0; r < 8; r++) {
            ulonglong2 h2 = *(const ulonglong2*)(sm + r * HSTRIDE + smoff + m * 4);
            acc[r][0] = fma2(h2.x, w2[0][2 * m + 0], acc[r][0]);
            acc[r][0] = fma2(h2.y, w2[0][2 * m + 1], acc[r][0]);
            acc[r][1] = fma2(h2.x, w2[1][2 * m + 0], acc[r][1]);
            acc[r][1] = fma2(h2.y, w2[1][2 * m + 1], acc[r][1]);
        }
    }
#pragma unroll
    for (int r = 0; r < 8; r++) {
#pragma unroll
        for (int c = 0; c < 2; c++) {
            float lo, hi;
            unpackf2(acc[r][c], lo, hi);
            part[seg * PSEG + r * PROW + cg * 2 + c] = lo + hi;
        }
    }
}

// ---------------------------------------------------------------------------
// Fused persistent kernel (R13 champion + post-mm_x h-load issue):
//   h_{t+1} = tanh( (x_t@W + b) + h_t@Wr )
// Per step: [loop top] tag-check (loads issued last iter, post-mm_x -> hot)
//   + STS hs -> S1 -> mm_r -> S2 -> reduce + tanh + tagged stcg -> S4 ->
//   stage xs (warp-own from xt regs) -> mm_x -> ISSUE h(t+1) tagged loads
//   (peers stored ~1024 cyc ago -> tags ready; RTT overlaps S6+reduce2)
//   -> S6 -> reduce2 -> xw_cur. xt <- x[t+1] prefetched at loop top.
// ---------------------------------------------------------------------------
__global__ void __launch_bounds__(256, 1) rnn_fused_kernel(
    const float* __restrict__ W,      // [512,512] row-major
    const float* __restrict__ Wr,     // [512,512] row-major
    const float* __restrict__ x,      // [64,1024,512]
    const float* __restrict__ bias,   // [512]
    float* __restrict__ out)          // [64,512]
{
    __shared__ float hs[TILEF];              // staged h tile   18 KB
    __shared__ float xs[TILEF];              // staged x tile   18 KB
    __shared__ float part[16 * PSEG];        // partials        16.9 KB

    const int tid  = threadIdx.x;
    const int w    = tid >> 5;               // warp: k-slice [w*64, +64)
    const int lane = tid & 31;
    const int cg   = lane >> 1;              // col pair
    const int ks   = lane & 1;               // k half
    const int c    = blockIdx.x;
    const int b0   = (c >> 4) * 8;
    const int j0   = (c & 15) * 32;

    const int kb    = w * 64 + ks * 32;
    const int smoff = w * 72 + ks * 36;
    const int seg   = w * 2 + ks;

    // persistent packed weights: (k, k+1) pairs for this thread's 2 columns
    unsigned long long wr2[2][16], wx2[2][16];
#pragma unroll
    for (int cc = 0; cc < 2; cc++) {
        const int j = j0 + cg * 2 + cc;
#pragma unroll
        for (int p = 0; p < 16; p++) {
            const int k = kb + 2 * p;
            wr2[cc][p] = packf2(Wr[(size_t)k * DIM + j], Wr[(size_t)(k + 1) * DIM + j]);
            wx2[cc][p] = packf2(W[(size_t)k * DIM + j],  W[(size_t)(k + 1) * DIM + j]);
        }
    }
    const int   rrow = tid >> 5;             // output row
    const int   rcol = tid & 31;             // output col
    const float bv   = bias[j0 + rcol];

    // this thread's tagged h slots (one per ping-pong buffer)
    uint2* const hslot0 = &g_h2[0][(b0 + rrow) * DIM + j0 + rcol];
    uint2* const hslot1 = &g_h2[1][(b0 + rrow) * DIM + j0 + rcol];

    // warp-chunk map for x prefetch / xs staging: float4 v -> (row, col4)
    const int sr0 = lane >> 3,        sc0 = lane & 7;         // v = lane
    const int sr1 = (lane + 32) >> 3, sc1 = (lane + 32) & 7;  // v = lane+32

    // ---- prologue: xs <- x[0] (warp-own chunks), mm_x, xw_cur for t=0 ----
    float4 xt[4];
#pragma unroll
    for (int pc = 0; pc < 2; pc++) {
        const int p = w * 2 + pc;
        float4 d0 = __ldg((const float4*)(x + ((size_t)(b0 + sr0) * TSTEPS + 0) * DIM + p * 32) + sc0);
        float4 d1 = __ldg((const float4*)(x + ((size_t)(b0 + sr1) * TSTEPS + 0) * DIM + p * 32) + sc1);
        *(float4*)&xs[sr0 * HSTRIDE + p * 36 + sc0 * 4] = d0;
        *(float4*)&xs[sr1 * HSTRIDE + p * 36 + sc1 * 4] = d1;
    }
    __syncwarp();
    mm_partials(xs, wx2, smoff, seg, cg, part);
    __syncthreads();
    float xw_cur = bv;
#pragma unroll
    for (int s8 = 0; s8 < 16; s8++) xw_cur += part[s8 * PSEG + rrow * PROW + rcol];
    __syncthreads();                         // guard part reuse by mm_r(0)

    // issue h(0) tagged loads (tags already 0 via memset -> immediate hits)
    uint4 a[8];
    {
        const char* hb = (const char*)(g_h2[0] + (size_t)b0 * DIM);
#pragma unroll
        for (int q = 0; q < 4; q++) {
            int idx = tid + q * 256;
            a[2 * q + 0] = ldcg_v4(hb + (size_t)idx * 32);
            a[2 * q + 1] = ldcg_v4(hb + (size_t)idx * 32 + 16);
        }
    }

    for (int t = 0; t < TSTEPS; t++) {
        // ---- tag check + retry stale vectors (loads issued last iteration) --
        const char* hb = (const char*)(g_h2[t & 1] + (size_t)b0 * DIM);
        {
            const unsigned want = (unsigned)t;
#pragma unroll
            for (int v = 0; v < 8; v++) {
                while ((a[v].y != want) | (a[v].w != want)) {
                    int idx = tid + (v >> 1) * 256;
                    a[v] = ldcg_v4(hb + (size_t)idx * 32 + (v & 1) * 16);
                }
            }
        }
#pragma unroll
        for (int q = 0; q < 4; q++) {
            int idx = tid + q * 256, row = idx >> 7, c4 = idx & 127;
            float4 hv4;
            hv4.x = __uint_as_float(a[2 * q + 0].x);
            hv4.y = __uint_as_float(a[2 * q + 0].z);
            hv4.z = __uint_as_float(a[2 * q + 1].x);
            hv4.w = __uint_as_float(a[2 * q + 1].z);
            *(float4*)&hs[sw_off(row, c4)] = hv4;
        }
        // ---- prefetch x[t+1] into regs (consumed post-S4) ----
        {
            const int tn = (t + 1 < TSTEPS) ? (t + 1) : (TSTEPS - 1);
#pragma unroll
            for (int pc = 0; pc < 2; pc++) {
                const int p = w * 2 + pc;
                xt[pc * 2 + 0] = __ldg((const float4*)(
                    x + ((size_t)(b0 + sr0) * TSTEPS + tn) * DIM + p * 32) + sc0);
                xt[pc * 2 + 1] = __ldg((const float4*)(
                    x + ((size_t)(b0 + sr1) * TSTEPS + tn) * DIM + p * 32) + sc1);
            }
        }
        __syncthreads();                     // S1: hs complete

        // ---- recurrence: h_t @ Wr -> part ----
        mm_partials(hs, wr2, smoff, seg, cg, part);
        __syncthreads();                     // S2: part complete

        // ---- reduce + tanh + tagged store ----
        float s = xw_cur;
#pragma unroll
        for (int s8 = 0; s8 < 16; s8++) s += part[s8 * PSEG + rrow * PROW + rcol];
        float hv = tanhf(s);
        if (t == TSTEPS - 1) {
            out[(b0 + rrow) * DIM + j0 + rcol] = hv;
            return;
        }
        stcg_v2(((t + 1) & 1) ? hslot1 : hslot0,
                __float_as_uint(hv), (unsigned)(t + 1));
        __syncthreads();                     // S4: part reads done -> reuse

        // ---- stage xs (warp-own chunks from regs) + mm_x -> part ----
#pragma unroll
        for (int pc = 0; pc < 2; pc++) {
            const int p = w * 2 + pc;
            *(float4*)&xs[sr0 * HSTRIDE + p * 36 + sc0 * 4] = xt[pc * 2 + 0];
            *(float4*)&xs[sr1 * HSTRIDE + p * 36 + sc1 * 4] = xt[pc * 2 + 1];
        }
        __syncwarp();
        mm_partials(xs, wx2, smoff, seg, cg, part);

        // ---- issue h(t+1) tagged loads: peers stored ~mm_x-duration ago ----
        {
            const char* hb2 = (const char*)(g_h2[(t + 1) & 1] + (size_t)b0 * DIM);
#pragma unroll
            for (int q = 0; q < 4; q++) {
                int idx = tid + q * 256;
                a[2 * q + 0] = ldcg_v4(hb2 + (size_t)idx * 32);
                a[2 * q + 1] = ldcg_v4(hb2 + (size_t)idx * 32 + 16);
            }
        }
        __syncthreads();                     // S6: part complete
        float s2 = bv;
#pragma unroll
        for (int s8 = 0; s8 < 16; s8++) s2 += part[s8 * PSEG + rrow * PROW + rcol];
        xw_cur = s2;
        // (no barrier needed before next S1: mm_r(t+1) writes part only after
        //  S1(t+1), and no warp passes S1(t+1) before all finish reduce2 reads)
    }
}

// ============================================================================
extern "C" void kernel_launch(void* const* d_in, const int* in_sizes, int n_in,
                              void* d_out, int out_size)
{
    const float* x    = (const float*)d_in[0];   // [64,1024,512]
    const float* W    = (const float*)d_in[1];   // [512,512]
    const float* Wr   = (const float*)d_in[2];   // [512,512]
    const float* bias = (const float*)d_in[3];   // [512]
    float* out = (float*)d_out;                  // [64,512]

    void* h_p; cudaGetSymbolAddress(&h_p, g_h2);

    // per-launch reset (graph-capturable, replay-safe):
    // zeroed pairs = (h=0.0f, tag=0) = exactly h_0 for t=0 consumers.
    cudaMemsetAsync(h_p, 0, sizeof(uint2) * 2 * BATCH * DIM);

    rnn_fused_kernel<<<NCTA, 256>>>(W, Wr, x, bias, out);
}

// round 17
// speedup vs baseline: 1.1540x; 1.1540x over previous
#include <cuda_runtime.h>

#define BATCH   64
#define TSTEPS  1024
#define DIM     512
#define NCTA    128          // 8 b-groups x 16 j-groups; co-resident
#define NBG     8
#define NJG     16

#define HSTRIDE 576          // staged row stride: 16 chunks x (32 data + 4 pad)
#define TILEF   (8 * HSTRIDE)
#define PROW    33
#define PSEG    (8 * PROW)

// ---------------- scratch (device globals; no allocations) ------------------
// h stored as (value, tag) pairs: tag == t  <=>  this word holds h_t.
// Ping-pong: h_t lives in buffer t&1. Zero-init = (0.0f, tag 0) = valid h_0.
__device__ uint2 g_h2[2][BATCH * DIM];       // 512 KB

// ---------------- f32x2 packed-FMA helpers (sm_100+) ------------------------
static __device__ __forceinline__ unsigned long long packf2(float lo, float hi) {
    unsigned long long r;
    asm("mov.b64 %0, {%1, %2};" : "=l"(r) : "f"(lo), "f"(hi));
    return r;
}
static __device__ __forceinline__ void unpackf2(unsigned long long v, float& lo, float& hi) {
    asm("mov.b64 {%0, %1}, %2;" : "=f"(lo), "=f"(hi) : "l"(v));
}
static __device__ __forceinline__ unsigned long long fma2(
    unsigned long long a, unsigned long long b, unsigned long long c) {
    unsigned long long d;
    asm("fma.rn.f32x2 %0, %1, %2, %3;" : "=l"(d) : "l"(a), "l"(b), "l"(c));
    return d;
}

// L2-coherent raw accessors for the tagged h buffer (the consumer's gate (tag)
// travels in the same 16B load as the values -> no fences, no atomics).
static __device__ __forceinline__ uint4 ldcg_v4(const void* p) {
    uint4 r;
    asm volatile("ld.global.cg.v4.b32 {%0,%1,%2,%3}, [%4];"
                 : "=r"(r.x), "=r"(r.y), "=r"(r.z), "=r"(r.w) : "l"(p));
    return r;
}
static __device__ __forceinline__ void stcg_v2(void* p, unsigned a, unsigned b) {
    asm volatile("st.global.cg.v2.b32 [%0], {%1,%2};"
                 :: "l"(p), "r"(a), "r"(b) : "memory");
}

// Padded staged-tile address: chunk ch at 36*ch floats (conflict-free LDS.128).
static __device__ __forceinline__ int sw_off(int row, int c4) {
    return row * HSTRIDE + c4 * 4 + (c4 >> 3) * 4;
}

// ---------------------------------------------------------------------------
// Matmul partials: warp w = k-slice 64, lane -> (cg: col pair, ks: k half).
// 8 rows x 2 cols over 32 k. 64 LDS.128 (conflict-free) + 256 fma2 per warp.
// Reads ONLY chunks 2w, 2w+1 of the staged tile.
// ---------------------------------------------------------------------------
static __device__ __forceinline__ void mm_partials(
    const float* __restrict__ sm, const unsigned long long w2[2][16],
    int smoff, int seg, int cg, float* __restrict__ part)
{
    unsigned long long acc[8][2];
#pragma unroll
    for (int r = 0; r < 8; r++) { acc[r][0] = 0ULL; acc[r][1] = 0ULL; }

#pragma unroll
    for (int m = 0; m < 8; m++) {
#pragma unroll
        for (int r = 0; r < 8; r++) {
            ulonglong2 h2 = *(const ulonglong2*)(sm + r * HSTRIDE + smoff + m * 4);
            acc[r][0] = fma2(h2.x, w2[0][2 * m + 0], acc[r][0]);
            acc[r][0] = fma2(h2.y, w2[0][2 * m + 1], acc[r][0]);
            acc[r][1] = fma2(h2.x, w2[1][2 * m + 0], acc[r][1]);
            acc[r][1] = fma2(h2.y, w2[1][2 * m + 1], acc[r][1]);
        }
    }
#pragma unroll
    for (int r = 0; r < 8; r++) {
#pragma unroll
        for (int c = 0; c < 2; c++) {
            float lo, hi;
            unpackf2(acc[r][c], lo, hi);
            part[seg * PSEG + r * PROW + cg * 2 + c] = lo + hi;
        }
    }
}

// ---------------------------------------------------------------------------
// Fused persistent kernel (R13 champion + batched retry + issue-order fixes):
//   h_{t+1} = tanh( (x_t@W + b) + h_t@Wr )
// Per step: [loop top] issue h_t tagged loads + x[t+1] prefetch -> batched
//   tag-check (one RTT per retry round) -> STS hs -> S1 -> mm_r -> S2 ->
//   reduce (2 chains) + tanh + tagged stcg -> S4 -> stage xs (warp-own) ->
//   mm_x -> S6 -> reduce2 (2 chains) -> xw_cur.
// ---------------------------------------------------------------------------
__global__ void __launch_bounds__(256, 1) rnn_fused_kernel(
    const float* __restrict__ W,      // [512,512] row-major
    const float* __restrict__ Wr,     // [512,512] row-major
    const float* __restrict__ x,      // [64,1024,512]
    const float* __restrict__ bias,   // [512]
    float* __restrict__ out)          // [64,512]
{
    __shared__ float hs[TILEF];              // staged h tile   18 KB
    __shared__ float xs[TILEF];              // staged x tile   18 KB
    __shared__ float part[16 * PSEG];        // partials        16.9 KB

    const int tid  = threadIdx.x;
    const int w    = tid >> 5;               // warp: k-slice [w*64, +64)
    const int lane = tid & 31;
    const int cg   = lane >> 1;              // col pair
    const int ks   = lane & 1;               // k half
    const int c    = blockIdx.x;
    const int b0   = (c >> 4) * 8;
    const int j0   = (c & 15) * 32;

    const int kb    = w * 64 + ks * 32;
    const int smoff = w * 72 + ks * 36;
    const int seg   = w * 2 + ks;

    // persistent packed weights: (k, k+1) pairs for this thread's 2 columns
    unsigned long long wr2[2][16], wx2[2][16];
#pragma unroll
    for (int cc = 0; cc < 2; cc++) {
        const int j = j0 + cg * 2 + cc;
#pragma unroll
        for (int p = 0; p < 16; p++) {
            const int k = kb + 2 * p;
            wr2[cc][p] = packf2(Wr[(size_t)k * DIM + j], Wr[(size_t)(k + 1) * DIM + j]);
            wx2[cc][p] = packf2(W[(size_t)k * DIM + j],  W[(size_t)(k + 1) * DIM + j]);
        }
    }
    const int   rrow = tid >> 5;             // output row
    const int   rcol = tid & 31;             // output col
    const float bv   = bias[j0 + rcol];

    // this thread's tagged h slots (one per ping-pong buffer)
    uint2* const hslot0 = &g_h2[0][(b0 + rrow) * DIM + j0 + rcol];
    uint2* const hslot1 = &g_h2[1][(b0 + rrow) * DIM + j0 + rcol];

    // warp-chunk map for x prefetch / xs staging: float4 v -> (row, col4)
    const int sr0 = lane >> 3,        sc0 = lane & 7;         // v = lane
    const int sr1 = (lane + 32) >> 3, sc1 = (lane + 32) & 7;  // v = lane+32

    // ---- prologue: xs <- x[0] (warp-own chunks), mm_x, xw_cur for t=0 ----
    float4 xt[4];
#pragma unroll
    for (int pc = 0; pc < 2; pc++) {
        const int p = w * 2 + pc;
        float4 d0 = __ldg((const float4*)(x + ((size_t)(b0 + sr0) * TSTEPS + 0) * DIM + p * 32) + sc0);
        float4 d1 = __ldg((const float4*)(x + ((size_t)(b0 + sr1) * TSTEPS + 0) * DIM + p * 32) + sc1);
        *(float4*)&xs[sr0 * HSTRIDE + p * 36 + sc0 * 4] = d0;
        *(float4*)&xs[sr1 * HSTRIDE + p * 36 + sc1 * 4] = d1;
    }
    __syncwarp();
    mm_partials(xs, wx2, smoff, seg, cg, part);
    __syncthreads();
    float xw_cur = bv;
#pragma unroll
    for (int s8 = 0; s8 < 16; s8++) xw_cur += part[s8 * PSEG + rrow * PROW + rcol];
    __syncthreads();                         // guard part reuse by mm_r(0)

    for (int t = 0; t < TSTEPS; t++) {
        // ---- issue h_t tagged loads (champion issue point), then x[t+1] ----
        const char* hb = (const char*)(g_h2[t & 1] + (size_t)b0 * DIM);
        uint4 a[8];
#pragma unroll
        for (int q = 0; q < 4; q++) {
            int idx = tid + q * 256;               // logical float4 in tile
            a[2 * q + 0] = ldcg_v4(hb + (size_t)idx * 32);
            a[2 * q + 1] = ldcg_v4(hb + (size_t)idx * 32 + 16);
        }
        {
            const int tn = (t + 1 < TSTEPS) ? (t + 1) : (TSTEPS - 1);
#pragma unroll
            for (int pc = 0; pc < 2; pc++) {
                const int p = w * 2 + pc;
                xt[pc * 2 + 0] = __ldg((const float4*)(
                    x + ((size_t)(b0 + sr0) * TSTEPS + tn) * DIM + p * 32) + sc0);
                xt[pc * 2 + 1] = __ldg((const float4*)(
                    x + ((size_t)(b0 + sr1) * TSTEPS + tn) * DIM + p * 32) + sc1);
            }
        }
        // ---- batched tag check: one L2 RTT per retry round (MLP re-issue) ---
        {
            const unsigned want = (unsigned)t;
            unsigned pend = 0u;
#pragma unroll
            for (int v = 0; v < 8; v++)
                if ((a[v].y != want) | (a[v].w != want)) pend |= (1u << v);
            while (pend) {
#pragma unroll
                for (int v = 0; v < 8; v++)
                    if (pend & (1u << v)) {
                        int idx = tid + (v >> 1) * 256;
                        a[v] = ldcg_v4(hb + (size_t)idx * 32 + (v & 1) * 16);
                    }
#pragma unroll
                for (int v = 0; v < 8; v++)
                    if ((a[v].y == want) & (a[v].w == want)) pend &= ~(1u << v);
            }
        }
#pragma unroll
        for (int q = 0; q < 4; q++) {
            int idx = tid + q * 256, row = idx >> 7, c4 = idx & 127;
            float4 hv4;
            hv4.x = __uint_as_float(a[2 * q + 0].x);
            hv4.y = __uint_as_float(a[2 * q + 0].z);
            hv4.z = __uint_as_float(a[2 * q + 1].x);
            hv4.w = __uint_as_float(a[2 * q + 1].z);
            *(float4*)&hs[sw_off(row, c4)] = hv4;
        }
        __syncthreads();                     // S1: hs complete

        // ---- recurrence: h_t @ Wr -> part ----
        mm_partials(hs, wr2, smoff, seg, cg, part);
        __syncthreads();                     // S2: part complete

        // ---- reduce (2 ILP chains) + tanh + tagged store ----
        float r0 = xw_cur, r1 = 0.f;
#pragma unroll
        for (int s8 = 0; s8 < 16; s8 += 2) {
            r0 += part[(s8 + 0) * PSEG + rrow * PROW + rcol];
            r1 += part[(s8 + 1) * PSEG + rrow * PROW + rcol];
        }
        float hv = tanhf(r0 + r1);
        if (t == TSTEPS - 1) {
            out[(b0 + rrow) * DIM + j0 + rcol] = hv;
            return;
        }
        stcg_v2(((t + 1) & 1) ? hslot1 : hslot0,
                __float_as_uint(hv), (unsigned)(t + 1));
        __syncthreads();                     // S4: part reads done -> reuse

        // ---- stage xs (warp-own chunks from regs) + mm_x -> part ----
#pragma unroll
        for (int pc = 0; pc < 2; pc++) {
            const int p = w * 2 + pc;
            *(float4*)&xs[sr0 * HSTRIDE + p * 36 + sc0 * 4] = xt[pc * 2 + 0];
            *(float4*)&xs[sr1 * HSTRIDE + p * 36 + sc1 * 4] = xt[pc * 2 + 1];
        }
        __syncwarp();
        mm_partials(xs, wx2, smoff, seg, cg, part);
        __syncthreads();                     // S6: part complete
        float s0 = bv, s1 = 0.f;
#pragma unroll
        for (int s8 = 0; s8 < 16; s8 += 2) {
            s0 += part[(s8 + 0) * PSEG + rrow * PROW + rcol];
            s1 += part[(s8 + 1) * PSEG + rrow * PROW + rcol];
        }
        xw_cur = s0 + s1;
        // (no barrier needed before next S1: mm_r(t+1) writes part only after
        //  S1(t+1), and no warp passes S1(t+1) before all finish reduce2 reads)
    }
}

// ============================================================================
extern "C" void kernel_launch(void* const* d_in, const int* in_sizes, int n_in,
                              void* d_out, int out_size)
{
    const float* x    = (const float*)d_in[0];   // [64,1024,512]
    const float* W    = (const float*)d_in[1];   // [512,512]
    const float* Wr   = (const float*)d_in[2];   // [512,512]
    const float* bias = (const float*)d_in[3];   // [512]
    float* out = (float*)d_out;                  // [64,512]

    void* h_p; cudaGetSymbolAddress(&h_p, g_h2);

    // per-launch reset (graph-capturable, replay-safe):
    // zeroed pairs = (h=0.0f, tag=0) = exactly h_0 for t=0 consumers.
    cudaMemsetAsync(h_p, 0, sizeof(uint2) * 2 * BATCH * DIM);

    rnn_fused_kernel<<<NCTA, 256>>>(W, Wr, x, bias, out);
}